// round 2
// baseline (speedup 1.0000x reference)
#include <cuda_runtime.h>

#define HD 2048
#define NH 16
#define DH 128
#define BB 2
#define SQ 2048
#define MR (BB*SQ)   // 4096 rows

// Scratch (device globals; no allocations allowed)
__device__ float g_Q[(size_t)MR*HD];
__device__ float g_K[(size_t)MR*HD];
__device__ float g_V[(size_t)MR*HD];
__device__ float g_A[(size_t)MR*HD];

// ---------------------------------------------------------------------------
// SGEMM: C[M,N] = A[M,K] @ W[K,N] + bias[N]
// 128x128 block tile, BK=16, 256 threads, 8x8 per-thread micro-tile.
// ---------------------------------------------------------------------------
__global__ __launch_bounds__(256) void gemm_bias_kernel(
    const float* __restrict__ A, const float* __restrict__ W,
    const float* __restrict__ bias, float* __restrict__ C,
    int M, int N, int K)
{
    __shared__ float As[16][132];   // transposed A tile: As[k][m]
    __shared__ float Bs[16][132];   // Bs[k][n]

    const int tid = threadIdx.x;
    const int bm  = blockIdx.y * 128;
    const int bn  = blockIdx.x * 128;
    const int tm  = (tid / 16) * 8;
    const int tn  = (tid % 16) * 8;

    float acc[8][8];
    #pragma unroll
    for (int i = 0; i < 8; i++)
        #pragma unroll
        for (int j = 0; j < 8; j++) acc[i][j] = 0.f;

    const int a_r  = tid / 4;        // 0..63 (+64 second iter)
    const int a_c4 = tid % 4;        // which float4 of the 16-wide k slab
    const int b_r  = tid / 32;       // 0..7 (+8 second iter)
    const int b_c4 = tid % 32;       // float4 col 0..31

    for (int k0 = 0; k0 < K; k0 += 16) {
        #pragma unroll
        for (int it = 0; it < 2; it++) {
            int r = a_r + it * 64;
            float4 v = *(const float4*)&A[(size_t)(bm + r) * K + k0 + a_c4 * 4];
            As[a_c4*4 + 0][r] = v.x;
            As[a_c4*4 + 1][r] = v.y;
            As[a_c4*4 + 2][r] = v.z;
            As[a_c4*4 + 3][r] = v.w;
        }
        #pragma unroll
        for (int it = 0; it < 2; it++) {
            int r = b_r + it * 8;
            float4 v = *(const float4*)&W[(size_t)(k0 + r) * N + bn + b_c4 * 4];
            *(float4*)&Bs[r][b_c4 * 4] = v;
        }
        __syncthreads();

        #pragma unroll
        for (int kk = 0; kk < 16; kk++) {
            float a[8], b[8];
            #pragma unroll
            for (int i = 0; i < 8; i += 4) {
                float4 t = *(const float4*)&As[kk][tm + i];
                a[i] = t.x; a[i+1] = t.y; a[i+2] = t.z; a[i+3] = t.w;
            }
            #pragma unroll
            for (int j = 0; j < 8; j += 4) {
                float4 t = *(const float4*)&Bs[kk][tn + j];
                b[j] = t.x; b[j+1] = t.y; b[j+2] = t.z; b[j+3] = t.w;
            }
            #pragma unroll
            for (int i = 0; i < 8; i++)
                #pragma unroll
                for (int j = 0; j < 8; j++)
                    acc[i][j] += a[i] * b[j];
        }
        __syncthreads();
    }

    #pragma unroll
    for (int i = 0; i < 8; i++) {
        #pragma unroll
        for (int j = 0; j < 8; j += 4) {
            float4 o;
            o.x = acc[i][j+0] + bias[bn + tn + j + 0];
            o.y = acc[i][j+1] + bias[bn + tn + j + 1];
            o.z = acc[i][j+2] + bias[bn + tn + j + 2];
            o.w = acc[i][j+3] + bias[bn + tn + j + 3];
            *(float4*)&C[(size_t)(bm + tm + i) * N + bn + tn + j] = o;
        }
    }
}

// ---------------------------------------------------------------------------
// Flash attention (fp32, online softmax).
// Grid: (S/64, NH, B). Block: 256 threads. 4 threads per q-row.
// Q/K/V layouts are [B,S,NH*DH] row-major (projection output), head slice
// is the contiguous 128 floats at column h*128.
// Thread (row, g): score columns c = 4*j + g (j=0..15); output dims
// d in [g*32, g*32+32).
// ---------------------------------------------------------------------------
#define PITCH 132
#define PPITCH 66

__global__ __launch_bounds__(256) void attn_kernel(
    const float* __restrict__ Q, const float* __restrict__ K,
    const float* __restrict__ V, const int* __restrict__ mask,
    float* __restrict__ O)
{
    extern __shared__ float sm[];
    float* Qs = sm;                    // 64 x 132
    float* Ks = Qs + 64 * PITCH;       // 64 x 132
    float* Vs = Ks + 64 * PITCH;       // 64 x 132
    float* Ps = Vs + 64 * PITCH;       // 64 x 66

    const int q0  = blockIdx.x * 64;
    const int h   = blockIdx.y;
    const int b   = blockIdx.z;
    const int tid = threadIdx.x;
    const int row = tid >> 2;          // 0..63
    const int g   = tid & 3;           // 0..3

    const size_t headbase = (size_t)b * SQ * HD + (size_t)h * DH;

    // Load Q tile (64 x 128) as float4
    #pragma unroll
    for (int it = 0; it < 8; it++) {
        int lin = it * 256 + tid;      // float4 index over 64*32
        int r = lin >> 5, c4 = lin & 31;
        float4 v = *(const float4*)&Q[headbase + (size_t)(q0 + r) * HD + c4 * 4];
        *(float4*)&Qs[r * PITCH + c4 * 4] = v;
    }

    float m = -1e30f, l = 0.f;
    float o[32];
    #pragma unroll
    for (int i = 0; i < 32; i++) o[i] = 0.f;

    const float scale = 0.08838834764831845f;   // 1/sqrt(128)
    const int* mrow = mask + ((size_t)b * SQ + (q0 + row)) * SQ;

    for (int k0 = 0; k0 < SQ; k0 += 64) {
        __syncthreads();   // previous iteration done with Ks/Vs

        #pragma unroll
        for (int it = 0; it < 8; it++) {
            int lin = it * 256 + tid;
            int r = lin >> 5, c4 = lin & 31;
            float4 kv = *(const float4*)&K[headbase + (size_t)(k0 + r) * HD + c4 * 4];
            *(float4*)&Ks[r * PITCH + c4 * 4] = kv;
            float4 vv = *(const float4*)&V[headbase + (size_t)(k0 + r) * HD + c4 * 4];
            *(float4*)&Vs[r * PITCH + c4 * 4] = vv;
        }
        __syncthreads();

        // scores for 16 columns c = 4*j + g
        float s[16];
        #pragma unroll
        for (int j = 0; j < 16; j++) s[j] = 0.f;

        const float* qr = &Qs[row * PITCH];
        #pragma unroll 4
        for (int d = 0; d < 128; d += 4) {
            float4 q4 = *(const float4*)&qr[d];
            #pragma unroll
            for (int j = 0; j < 16; j++) {
                float4 k4 = *(const float4*)&Ks[(4*j + g) * PITCH + d];
                s[j] += q4.x * k4.x + q4.y * k4.y + q4.z * k4.z + q4.w * k4.w;
            }
        }

        float tmax = -1e30f;
        #pragma unroll
        for (int j = 0; j < 16; j++) {
            float sv = s[j] * scale;
            if (mrow[k0 + 4*j + g] == 0) sv = -1e30f;
            s[j] = sv;
            tmax = fmaxf(tmax, sv);
        }
        tmax = fmaxf(tmax, __shfl_xor_sync(0xffffffffu, tmax, 1));
        tmax = fmaxf(tmax, __shfl_xor_sync(0xffffffffu, tmax, 2));

        float mnew = fmaxf(m, tmax);
        float corr = __expf(m - mnew);
        float psum = 0.f;
        #pragma unroll
        for (int j = 0; j < 16; j++) {
            float p = __expf(s[j] - mnew);
            Ps[row * PPITCH + 4*j + g] = p;
            psum += p;
        }
        psum += __shfl_xor_sync(0xffffffffu, psum, 1);
        psum += __shfl_xor_sync(0xffffffffu, psum, 2);
        l = l * corr + psum;
        m = mnew;

        #pragma unroll
        for (int i = 0; i < 32; i++) o[i] *= corr;

        __syncwarp();      // Ps for this row written by lanes of same warp

        // O accumulation: d chunk [g*32, g*32+32)
        for (int c = 0; c < 64; c++) {
            float p = Ps[row * PPITCH + c];
            const float* vr = &Vs[c * PITCH + g * 32];
            #pragma unroll
            for (int i = 0; i < 32; i += 4) {
                float4 v4 = *(const float4*)&vr[i];
                o[i+0] += p * v4.x;
                o[i+1] += p * v4.y;
                o[i+2] += p * v4.z;
                o[i+3] += p * v4.w;
            }
        }
    }

    float inv = 1.f / l;
    float* orow = &O[headbase + (size_t)(q0 + row) * HD + g * 32];
    #pragma unroll
    for (int i = 0; i < 32; i += 4) {
        float4 v;
        v.x = o[i+0] * inv;
        v.y = o[i+1] * inv;
        v.z = o[i+2] * inv;
        v.w = o[i+3] * inv;
        *(float4*)&orow[i] = v;
    }
}

// ---------------------------------------------------------------------------

extern "C" void kernel_launch(void* const* d_in, const int* in_sizes, int n_in,
                              void* d_out, int out_size)
{
    const float* X   = (const float*)d_in[0];
    const int*   msk = (const int*)  d_in[1];
    const float* Wq  = (const float*)d_in[2];
    const float* bq  = (const float*)d_in[3];
    const float* Wk  = (const float*)d_in[4];
    const float* bk  = (const float*)d_in[5];
    const float* Wv  = (const float*)d_in[6];
    const float* bv  = (const float*)d_in[7];
    const float* Wo  = (const float*)d_in[8];
    const float* bo  = (const float*)d_in[9];
    float* out = (float*)d_out;

    float *Qp, *Kp, *Vp, *Ap;
    cudaGetSymbolAddress((void**)&Qp, g_Q);
    cudaGetSymbolAddress((void**)&Kp, g_K);
    cudaGetSymbolAddress((void**)&Vp, g_V);
    cudaGetSymbolAddress((void**)&Ap, g_A);

    dim3 gg(HD / 128, MR / 128);     // (16, 32)
    dim3 gb(256);

    gemm_bias_kernel<<<gg, gb>>>(X, Wq, bq, Qp, MR, HD, HD);
    gemm_bias_kernel<<<gg, gb>>>(X, Wk, bk, Kp, MR, HD, HD);
    gemm_bias_kernel<<<gg, gb>>>(X, Wv, bv, Vp, MR, HD, HD);

    const int smem = (3 * 64 * PITCH + 64 * PPITCH) * (int)sizeof(float);
    cudaFuncSetAttribute(attn_kernel, cudaFuncAttributeMaxDynamicSharedMemorySize, smem);
    dim3 ga(SQ / 64, NH, BB);        // (32, 16, 2)
    attn_kernel<<<ga, 256, smem>>>(Qp, Kp, Vp, msk, Ap);

    gemm_bias_kernel<<<gg, gb>>>(Ap, Wo, bo, out, MR, HD, HD);
}

// round 5
// speedup vs baseline: 1.1638x; 1.1638x over previous
#include <cuda_runtime.h>
#include <cuda_bf16.h>
#include <cstdint>

#define HD 2048
#define NH 16
#define DH 128
#define BB 2
#define SQ 2048
#define MR (BB*SQ)   // 4096 rows

// ---------------------------------------------------------------------------
// Scratch (device globals; no allocations allowed)
// ---------------------------------------------------------------------------
__device__ float g_Q[(size_t)MR*HD];
__device__ float g_K[(size_t)MR*HD];
__device__ float g_V[(size_t)MR*HD];
__device__ float g_A[(size_t)MR*HD];
__device__ __nv_bfloat16 g_Xhi[(size_t)MR*HD];
__device__ __nv_bfloat16 g_Xlo[(size_t)MR*HD];
__device__ __nv_bfloat16 g_Ahi[(size_t)MR*HD];
__device__ __nv_bfloat16 g_Alo[(size_t)MR*HD];
__device__ __nv_bfloat16 g_Wthi[4][(size_t)HD*HD];   // transposed: [n][k]
__device__ __nv_bfloat16 g_Wtlo[4][(size_t)HD*HD];

// ---------------------------------------------------------------------------
// PTX helpers (compute_103-safe: mma.sync / ldmatrix / cp.async only)
// ---------------------------------------------------------------------------
__device__ __forceinline__ uint32_t smem_to_u32(const void* p) {
    uint32_t a;
    asm("{ .reg .u64 t; cvta.to.shared.u64 t, %1; cvt.u32.u64 %0, t; }"
        : "=r"(a) : "l"(p));
    return a;
}
__device__ __forceinline__ void cp_async16(uint32_t s, const void* g) {
    asm volatile("cp.async.cg.shared.global [%0], [%1], 16;" :: "r"(s), "l"(g));
}
#define CP_COMMIT() asm volatile("cp.async.commit_group;" ::: "memory")
#define CP_WAIT(n)  asm volatile("cp.async.wait_group %0;" :: "n"(n) : "memory")

__device__ __forceinline__ void ldsm_x4(uint32_t& r0, uint32_t& r1,
                                        uint32_t& r2, uint32_t& r3, uint32_t addr) {
    asm volatile("ldmatrix.sync.aligned.m8n8.x4.shared.b16 {%0,%1,%2,%3}, [%4];"
        : "=r"(r0), "=r"(r1), "=r"(r2), "=r"(r3) : "r"(addr));
}
__device__ __forceinline__ void mma_bf16(float* c, const uint32_t* a,
                                         uint32_t b0, uint32_t b1) {
    asm volatile(
        "mma.sync.aligned.m16n8k16.row.col.f32.bf16.bf16.f32 "
        "{%0,%1,%2,%3}, {%4,%5,%6,%7}, {%8,%9}, {%0,%1,%2,%3};"
        : "+f"(c[0]), "+f"(c[1]), "+f"(c[2]), "+f"(c[3])
        : "r"(a[0]), "r"(a[1]), "r"(a[2]), "r"(a[3]), "r"(b0), "r"(b1));
}

// ---------------------------------------------------------------------------
// Conversion kernels: fp32 -> (bf16 hi, bf16 lo) split
// ---------------------------------------------------------------------------
__global__ __launch_bounds__(256) void cvt_split_kernel(
    const float4* __restrict__ in, __nv_bfloat16* __restrict__ hi,
    __nv_bfloat16* __restrict__ lo, int n4)
{
    int i = blockIdx.x * 256 + threadIdx.x;
    if (i >= n4) return;
    float4 v = in[i];
    float f[4] = {v.x, v.y, v.z, v.w};
    __nv_bfloat162 h2[2], l2[2];
    #pragma unroll
    for (int p = 0; p < 2; p++) {
        __nv_bfloat16 h0 = __float2bfloat16(f[2*p+0]);
        __nv_bfloat16 h1 = __float2bfloat16(f[2*p+1]);
        __nv_bfloat16 l0 = __float2bfloat16(f[2*p+0] - __bfloat162float(h0));
        __nv_bfloat16 l1 = __float2bfloat16(f[2*p+1] - __bfloat162float(h1));
        h2[p] = __nv_bfloat162(h0, h1);
        l2[p] = __nv_bfloat162(l0, l1);
    }
    ((__nv_bfloat162*)hi)[2*i+0] = h2[0];
    ((__nv_bfloat162*)hi)[2*i+1] = h2[1];
    ((__nv_bfloat162*)lo)[2*i+0] = l2[0];
    ((__nv_bfloat162*)lo)[2*i+1] = l2[1];
}

// W[K,N] fp32 (N contiguous) -> Wt[n][k] bf16 hi/lo (K contiguous)
__global__ __launch_bounds__(256) void cvt_wt_kernel(
    const float* __restrict__ W, __nv_bfloat16* __restrict__ hi,
    __nv_bfloat16* __restrict__ lo)
{
    __shared__ float tile[32][33];
    const int n0 = blockIdx.x * 32, k0 = blockIdx.y * 32;
    const int tx = threadIdx.x, ty = threadIdx.y;   // block (32, 8)
    #pragma unroll
    for (int i = 0; i < 4; i++)
        tile[ty + 8*i][tx] = W[(size_t)(k0 + ty + 8*i) * HD + n0 + tx];
    __syncthreads();
    #pragma unroll
    for (int i = 0; i < 4; i++) {
        float v = tile[tx][ty + 8*i];    // = W[k0+tx][n0+ty+8i]
        __nv_bfloat16 h = __float2bfloat16(v);
        __nv_bfloat16 l = __float2bfloat16(v - __bfloat162float(h));
        size_t idx = (size_t)(n0 + ty + 8*i) * HD + k0 + tx;
        hi[idx] = h;
        lo[idx] = l;
    }
}

// ---------------------------------------------------------------------------
// mma.sync GEMM: C[M,N] = A[M,K] @ Bt[N,K]^T + bias, bf16 2-term split.
// CTA 128x128, K-chunk 32, 8 warps (2x4), warp tile 64x32.
// cp.async 2-stage double buffer. A row-major, Bt row-major = B col-major
// => ldmatrix without .trans for both operands.
// ---------------------------------------------------------------------------
#define KC 32
#define PITCHB 80                       // bytes per smem row (20 banks: conflict-free ldsm)
#define TILE_BYTES (128 * PITCHB)       // 10240
#define STAGE_BYTES (4 * TILE_BYTES)    // 40960: AH, AL, BH, BL
#define GEMM_SMEM (2 * STAGE_BYTES)     // 81920

__global__ __launch_bounds__(256, 1) void gemm_mma_kernel(
    const __nv_bfloat16* __restrict__ Ahi, const __nv_bfloat16* __restrict__ Alo,
    const __nv_bfloat16* __restrict__ Bhi, const __nv_bfloat16* __restrict__ Blo,
    const float* __restrict__ bias, float* __restrict__ C)
{
    extern __shared__ __align__(128) char smem[];
    const uint32_t sbase = smem_to_u32(smem);
    const int tid  = threadIdx.x;
    const int wid  = tid >> 5;
    const int lane = tid & 31;
    const int bm = blockIdx.y * 128;
    const int bn = blockIdx.x * 128;
    const int wm = (wid >> 2) * 64;     // warp row offset in CTA tile
    const int wn = (wid & 3) * 32;      // warp col offset

    float acc[4][4][4];
    #pragma unroll
    for (int mt = 0; mt < 4; mt++)
        #pragma unroll
        for (int nt = 0; nt < 4; nt++)
            #pragma unroll
            for (int i = 0; i < 4; i++) acc[mt][nt][i] = 0.f;

    const int lr = tid >> 2;            // 0..63  (row for cp.async, +64 on 2nd iter)
    const int lc = tid & 3;             // 16B chunk 0..3

    // prologue: stage 0
    {
        const uint32_t sb = sbase;
        #pragma unroll
        for (int i = 0; i < 2; i++) {
            int r = lr + i * 64;
            uint32_t off = (uint32_t)r * PITCHB + lc * 16;
            size_t ga = (size_t)(bm + r) * HD + lc * 8;
            size_t gb = (size_t)(bn + r) * HD + lc * 8;
            cp_async16(sb + 0*TILE_BYTES + off, Ahi + ga);
            cp_async16(sb + 1*TILE_BYTES + off, Alo + ga);
            cp_async16(sb + 2*TILE_BYTES + off, Bhi + gb);
            cp_async16(sb + 3*TILE_BYTES + off, Blo + gb);
        }
        CP_COMMIT();
    }

    const int r8 = lane & 7;
    const int g  = lane >> 3;
    const uint32_t a_row_add  = (uint32_t)(r8 + ((g & 1) ? 8 : 0)) * PITCHB + ((g & 2) ? 16 : 0);
    const uint32_t b_row_add  = (uint32_t)(r8 + ((g >= 2) ? 8 : 0)) * PITCHB + ((g & 1) ? 16 : 0);

    for (int t = 0; t < HD / KC; t++) {
        if (t + 1 < HD / KC) {
            const int k0 = (t + 1) * KC;
            const uint32_t sb = sbase + ((t + 1) & 1) * STAGE_BYTES;
            #pragma unroll
            for (int i = 0; i < 2; i++) {
                int r = lr + i * 64;
                uint32_t off = (uint32_t)r * PITCHB + lc * 16;
                size_t ga = (size_t)(bm + r) * HD + k0 + lc * 8;
                size_t gb = (size_t)(bn + r) * HD + k0 + lc * 8;
                cp_async16(sb + 0*TILE_BYTES + off, Ahi + ga);
                cp_async16(sb + 1*TILE_BYTES + off, Alo + ga);
                cp_async16(sb + 2*TILE_BYTES + off, Bhi + gb);
                cp_async16(sb + 3*TILE_BYTES + off, Blo + gb);
            }
            CP_COMMIT();
            CP_WAIT(1);
        } else {
            CP_WAIT(0);
        }
        __syncthreads();

        const uint32_t sb = sbase + (t & 1) * STAGE_BYTES;
        #pragma unroll
        for (int ks = 0; ks < 2; ks++) {
            uint32_t ah[4][4], al[4][4], bh[2][4], bl[2][4];
            #pragma unroll
            for (int mt = 0; mt < 4; mt++) {
                uint32_t addr = sb + (uint32_t)(wm + mt * 16) * PITCHB + ks * 32 + a_row_add;
                ldsm_x4(ah[mt][0], ah[mt][1], ah[mt][2], ah[mt][3], addr + 0*TILE_BYTES);
                ldsm_x4(al[mt][0], al[mt][1], al[mt][2], al[mt][3], addr + 1*TILE_BYTES);
            }
            #pragma unroll
            for (int p = 0; p < 2; p++) {
                uint32_t addr = sb + (uint32_t)(wn + p * 16) * PITCHB + ks * 32 + b_row_add;
                ldsm_x4(bh[p][0], bh[p][1], bh[p][2], bh[p][3], addr + 2*TILE_BYTES);
                ldsm_x4(bl[p][0], bl[p][1], bl[p][2], bl[p][3], addr + 3*TILE_BYTES);
            }
            #pragma unroll
            for (int mt = 0; mt < 4; mt++) {
                #pragma unroll
                for (int nt = 0; nt < 4; nt++) {
                    uint32_t bh0 = bh[nt >> 1][(nt & 1) * 2 + 0];
                    uint32_t bh1 = bh[nt >> 1][(nt & 1) * 2 + 1];
                    uint32_t bl0 = bl[nt >> 1][(nt & 1) * 2 + 0];
                    uint32_t bl1 = bl[nt >> 1][(nt & 1) * 2 + 1];
                    mma_bf16(acc[mt][nt], ah[mt], bh0, bh1);   // hi*hi
                    mma_bf16(acc[mt][nt], ah[mt], bl0, bl1);   // hi*lo
                    mma_bf16(acc[mt][nt], al[mt], bh0, bh1);   // lo*hi
                }
            }
        }
        __syncthreads();
    }

    // Epilogue: direct float2 stores + bias
    const int er = lane >> 2;           // 0..7
    const int ec = (lane & 3) * 2;
    #pragma unroll
    for (int mt = 0; mt < 4; mt++) {
        #pragma unroll
        for (int nt = 0; nt < 4; nt++) {
            int row = bm + wm + mt * 16 + er;
            int col = bn + wn + nt * 8 + ec;
            float b0 = bias[col], b1 = bias[col + 1];
            float2 v0 = make_float2(acc[mt][nt][0] + b0, acc[mt][nt][1] + b1);
            float2 v1 = make_float2(acc[mt][nt][2] + b0, acc[mt][nt][3] + b1);
            *(float2*)&C[(size_t)row * HD + col] = v0;
            *(float2*)&C[(size_t)(row + 8) * HD + col] = v1;
        }
    }
}

// ---------------------------------------------------------------------------
// Flash attention (fp32, online softmax) — unchanged (passing since round 2).
// ---------------------------------------------------------------------------
#define PITCH 132
#define PPITCH 66

__global__ __launch_bounds__(256) void attn_kernel(
    const float* __restrict__ Q, const float* __restrict__ K,
    const float* __restrict__ V, const int* __restrict__ mask,
    float* __restrict__ O)
{
    extern __shared__ float sm[];
    float* Qs = sm;
    float* Ks = Qs + 64 * PITCH;
    float* Vs = Ks + 64 * PITCH;
    float* Ps = Vs + 64 * PITCH;

    const int q0  = blockIdx.x * 64;
    const int h   = blockIdx.y;
    const int b   = blockIdx.z;
    const int tid = threadIdx.x;
    const int row = tid >> 2;
    const int g   = tid & 3;

    const size_t headbase = (size_t)b * SQ * HD + (size_t)h * DH;

    #pragma unroll
    for (int it = 0; it < 8; it++) {
        int lin = it * 256 + tid;
        int r = lin >> 5, c4 = lin & 31;
        float4 v = *(const float4*)&Q[headbase + (size_t)(q0 + r) * HD + c4 * 4];
        *(float4*)&Qs[r * PITCH + c4 * 4] = v;
    }

    float m = -1e30f, l = 0.f;
    float o[32];
    #pragma unroll
    for (int i = 0; i < 32; i++) o[i] = 0.f;

    const float scale = 0.08838834764831845f;
    const int* mrow = mask + ((size_t)b * SQ + (q0 + row)) * SQ;

    for (int k0 = 0; k0 < SQ; k0 += 64) {
        __syncthreads();

        #pragma unroll
        for (int it = 0; it < 8; it++) {
            int lin = it * 256 + tid;
            int r = lin >> 5, c4 = lin & 31;
            float4 kv = *(const float4*)&K[headbase + (size_t)(k0 + r) * HD + c4 * 4];
            *(float4*)&Ks[r * PITCH + c4 * 4] = kv;
            float4 vv = *(const float4*)&V[headbase + (size_t)(k0 + r) * HD + c4 * 4];
            *(float4*)&Vs[r * PITCH + c4 * 4] = vv;
        }
        __syncthreads();

        float s[16];
        #pragma unroll
        for (int j = 0; j < 16; j++) s[j] = 0.f;

        const float* qr = &Qs[row * PITCH];
        #pragma unroll 4
        for (int d = 0; d < 128; d += 4) {
            float4 q4 = *(const float4*)&qr[d];
            #pragma unroll
            for (int j = 0; j < 16; j++) {
                float4 k4 = *(const float4*)&Ks[(4*j + g) * PITCH + d];
                s[j] += q4.x * k4.x + q4.y * k4.y + q4.z * k4.z + q4.w * k4.w;
            }
        }

        float tmax = -1e30f;
        #pragma unroll
        for (int j = 0; j < 16; j++) {
            float sv = s[j] * scale;
            if (mrow[k0 + 4*j + g] == 0) sv = -1e30f;
            s[j] = sv;
            tmax = fmaxf(tmax, sv);
        }
        tmax = fmaxf(tmax, __shfl_xor_sync(0xffffffffu, tmax, 1));
        tmax = fmaxf(tmax, __shfl_xor_sync(0xffffffffu, tmax, 2));

        float mnew = fmaxf(m, tmax);
        float corr = __expf(m - mnew);
        float psum = 0.f;
        #pragma unroll
        for (int j = 0; j < 16; j++) {
            float p = __expf(s[j] - mnew);
            Ps[row * PPITCH + 4*j + g] = p;
            psum += p;
        }
        psum += __shfl_xor_sync(0xffffffffu, psum, 1);
        psum += __shfl_xor_sync(0xffffffffu, psum, 2);
        l = l * corr + psum;
        m = mnew;

        #pragma unroll
        for (int i = 0; i < 32; i++) o[i] *= corr;

        __syncwarp();

        for (int c = 0; c < 64; c++) {
            float p = Ps[row * PPITCH + c];
            const float* vr = &Vs[c * PITCH + g * 32];
            #pragma unroll
            for (int i = 0; i < 32; i += 4) {
                float4 v4 = *(const float4*)&vr[i];
                o[i+0] += p * v4.x;
                o[i+1] += p * v4.y;
                o[i+2] += p * v4.z;
                o[i+3] += p * v4.w;
            }
        }
    }

    float inv = 1.f / l;
    float* orow = &O[headbase + (size_t)(q0 + row) * HD + g * 32];
    #pragma unroll
    for (int i = 0; i < 32; i += 4) {
        float4 v;
        v.x = o[i+0] * inv;
        v.y = o[i+1] * inv;
        v.z = o[i+2] * inv;
        v.w = o[i+3] * inv;
        *(float4*)&orow[i] = v;
    }
}

// ---------------------------------------------------------------------------

extern "C" void kernel_launch(void* const* d_in, const int* in_sizes, int n_in,
                              void* d_out, int out_size)
{
    const float* X   = (const float*)d_in[0];
    const int*   msk = (const int*)  d_in[1];
    const float* Wq  = (const float*)d_in[2];
    const float* bq  = (const float*)d_in[3];
    const float* Wk  = (const float*)d_in[4];
    const float* bk  = (const float*)d_in[5];
    const float* Wv  = (const float*)d_in[6];
    const float* bv  = (const float*)d_in[7];
    const float* Wo  = (const float*)d_in[8];
    const float* bo  = (const float*)d_in[9];
    float* out = (float*)d_out;

    float *Qp, *Kp, *Vp, *Ap;
    __nv_bfloat16 *Xhi, *Xlo, *Ahi, *Alo, *Wthi, *Wtlo;
    cudaGetSymbolAddress((void**)&Qp, g_Q);
    cudaGetSymbolAddress((void**)&Kp, g_K);
    cudaGetSymbolAddress((void**)&Vp, g_V);
    cudaGetSymbolAddress((void**)&Ap, g_A);
    cudaGetSymbolAddress((void**)&Xhi, g_Xhi);
    cudaGetSymbolAddress((void**)&Xlo, g_Xlo);
    cudaGetSymbolAddress((void**)&Ahi, g_Ahi);
    cudaGetSymbolAddress((void**)&Alo, g_Alo);
    cudaGetSymbolAddress((void**)&Wthi, g_Wthi);
    cudaGetSymbolAddress((void**)&Wtlo, g_Wtlo);

    const size_t WSZ = (size_t)HD * HD;
    const int n4 = MR * HD / 4;

    cudaFuncSetAttribute(gemm_mma_kernel,
                         cudaFuncAttributeMaxDynamicSharedMemorySize, GEMM_SMEM);

    // 1. bf16 hi/lo splits of X and transposed weights
    cvt_split_kernel<<<n4 / 256, 256>>>((const float4*)X, Xhi, Xlo, n4);
    dim3 wg(HD / 32, HD / 32), wb(32, 8);
    cvt_wt_kernel<<<wg, wb>>>(Wq, Wthi + 0*WSZ, Wtlo + 0*WSZ);
    cvt_wt_kernel<<<wg, wb>>>(Wk, Wthi + 1*WSZ, Wtlo + 1*WSZ);
    cvt_wt_kernel<<<wg, wb>>>(Wv, Wthi + 2*WSZ, Wtlo + 2*WSZ);
    cvt_wt_kernel<<<wg, wb>>>(Wo, Wthi + 3*WSZ, Wtlo + 3*WSZ);

    // 2. Q/K/V projections on tensor cores (mma.sync)
    dim3 gg(HD / 128, MR / 128);   // (16, 32)
    gemm_mma_kernel<<<gg, 256, GEMM_SMEM>>>(Xhi, Xlo, Wthi + 0*WSZ, Wtlo + 0*WSZ, bq, Qp);
    gemm_mma_kernel<<<gg, 256, GEMM_SMEM>>>(Xhi, Xlo, Wthi + 1*WSZ, Wtlo + 1*WSZ, bk, Kp);
    gemm_mma_kernel<<<gg, 256, GEMM_SMEM>>>(Xhi, Xlo, Wthi + 2*WSZ, Wtlo + 2*WSZ, bv, Vp);

    // 3. attention
    const int smem = (3 * 64 * PITCH + 64 * PPITCH) * (int)sizeof(float);
    cudaFuncSetAttribute(attn_kernel, cudaFuncAttributeMaxDynamicSharedMemorySize, smem);
    dim3 ga(SQ / 64, NH, BB);
    attn_kernel<<<ga, 256, smem>>>(Qp, Kp, Vp, msk, Ap);

    // 4. output projection
    cvt_split_kernel<<<n4 / 256, 256>>>((const float4*)Ap, Ahi, Alo, n4);
    gemm_mma_kernel<<<gg, 256, GEMM_SMEM>>>(Ahi, Alo, Wthi + 3*WSZ, Wtlo + 3*WSZ, bo, out);
}

// round 6
// speedup vs baseline: 5.9828x; 5.1408x over previous
#include <cuda_runtime.h>
#include <cuda_bf16.h>
#include <cstdint>

#define HD 2048
#define NH 16
#define DH 128
#define BB 2
#define SQ 2048
#define MR (BB*SQ)   // 4096 rows

// ---------------------------------------------------------------------------
// Scratch (device globals; no allocations allowed)
// ---------------------------------------------------------------------------
__device__ __nv_bfloat16 g_Qhi[(size_t)MR*HD];
__device__ __nv_bfloat16 g_Qlo[(size_t)MR*HD];
__device__ __nv_bfloat16 g_Khi[(size_t)MR*HD];
__device__ __nv_bfloat16 g_Klo[(size_t)MR*HD];
__device__ __nv_bfloat16 g_Vhi[(size_t)MR*HD];
__device__ __nv_bfloat16 g_Vlo[(size_t)MR*HD];
__device__ __nv_bfloat16 g_Ahi[(size_t)MR*HD];
__device__ __nv_bfloat16 g_Alo[(size_t)MR*HD];
__device__ __nv_bfloat16 g_Xhi[(size_t)MR*HD];
__device__ __nv_bfloat16 g_Xlo[(size_t)MR*HD];
__device__ __nv_bfloat16 g_Wthi[4][(size_t)HD*HD];   // transposed: [n][k]
__device__ __nv_bfloat16 g_Wtlo[4][(size_t)HD*HD];

// ---------------------------------------------------------------------------
// PTX helpers (compute_103-safe: mma.sync / ldmatrix / cp.async only)
// ---------------------------------------------------------------------------
__device__ __forceinline__ uint32_t smem_to_u32(const void* p) {
    uint32_t a;
    asm("{ .reg .u64 t; cvta.to.shared.u64 t, %1; cvt.u32.u64 %0, t; }"
        : "=r"(a) : "l"(p));
    return a;
}
__device__ __forceinline__ void cp_async16(uint32_t s, const void* g) {
    asm volatile("cp.async.cg.shared.global [%0], [%1], 16;" :: "r"(s), "l"(g));
}
#define CP_COMMIT() asm volatile("cp.async.commit_group;" ::: "memory")
#define CP_WAIT(n)  asm volatile("cp.async.wait_group %0;" :: "n"(n) : "memory")

__device__ __forceinline__ void ldsm_x4(uint32_t& r0, uint32_t& r1,
                                        uint32_t& r2, uint32_t& r3, uint32_t addr) {
    asm volatile("ldmatrix.sync.aligned.m8n8.x4.shared.b16 {%0,%1,%2,%3}, [%4];"
        : "=r"(r0), "=r"(r1), "=r"(r2), "=r"(r3) : "r"(addr));
}
__device__ __forceinline__ void ldsm_x4_t(uint32_t& r0, uint32_t& r1,
                                          uint32_t& r2, uint32_t& r3, uint32_t addr) {
    asm volatile("ldmatrix.sync.aligned.m8n8.x4.trans.shared.b16 {%0,%1,%2,%3}, [%4];"
        : "=r"(r0), "=r"(r1), "=r"(r2), "=r"(r3) : "r"(addr));
}
__device__ __forceinline__ void mma_bf16(float* c, const uint32_t* a,
                                         uint32_t b0, uint32_t b1) {
    asm volatile(
        "mma.sync.aligned.m16n8k16.row.col.f32.bf16.bf16.f32 "
        "{%0,%1,%2,%3}, {%4,%5,%6,%7}, {%8,%9}, {%0,%1,%2,%3};"
        : "+f"(c[0]), "+f"(c[1]), "+f"(c[2]), "+f"(c[3])
        : "r"(a[0]), "r"(a[1]), "r"(a[2]), "r"(a[3]), "r"(b0), "r"(b1));
}
__device__ __forceinline__ uint32_t pack_bf2(__nv_bfloat16 a, __nv_bfloat16 b) {
    __nv_bfloat162 t(a, b);            // .x = low half = first element
    return *(uint32_t*)&t;
}
// split (x,y) into packed bf16 hi pair + bf16 lo (residual) pair
__device__ __forceinline__ void split_pack(float x, float y, uint32_t& hi, uint32_t& lo) {
    __nv_bfloat16 hx = __float2bfloat16(x);
    __nv_bfloat16 hy = __float2bfloat16(y);
    __nv_bfloat16 lx = __float2bfloat16(x - __bfloat162float(hx));
    __nv_bfloat16 ly = __float2bfloat16(y - __bfloat162float(hy));
    hi = pack_bf2(hx, hy);
    lo = pack_bf2(lx, ly);
}

// ---------------------------------------------------------------------------
// Conversion kernels: fp32 -> (bf16 hi, bf16 lo) split
// ---------------------------------------------------------------------------
__global__ __launch_bounds__(256) void cvt_split_kernel(
    const float4* __restrict__ in, __nv_bfloat16* __restrict__ hi,
    __nv_bfloat16* __restrict__ lo, int n4)
{
    int i = blockIdx.x * 256 + threadIdx.x;
    if (i >= n4) return;
    float4 v = in[i];
    float f[4] = {v.x, v.y, v.z, v.w};
    #pragma unroll
    for (int p = 0; p < 2; p++) {
        uint32_t h, l;
        split_pack(f[2*p+0], f[2*p+1], h, l);
        ((uint32_t*)hi)[2*i+p] = h;
        ((uint32_t*)lo)[2*i+p] = l;
    }
}

// W[K,N] fp32 (N contiguous) -> Wt[n][k] bf16 hi/lo (K contiguous)
__global__ __launch_bounds__(256) void cvt_wt_kernel(
    const float* __restrict__ W, __nv_bfloat16* __restrict__ hi,
    __nv_bfloat16* __restrict__ lo)
{
    __shared__ float tile[32][33];
    const int n0 = blockIdx.x * 32, k0 = blockIdx.y * 32;
    const int tx = threadIdx.x, ty = threadIdx.y;   // block (32, 8)
    #pragma unroll
    for (int i = 0; i < 4; i++)
        tile[ty + 8*i][tx] = W[(size_t)(k0 + ty + 8*i) * HD + n0 + tx];
    __syncthreads();
    #pragma unroll
    for (int i = 0; i < 4; i++) {
        float v = tile[tx][ty + 8*i];    // = W[k0+tx][n0+ty+8i]
        __nv_bfloat16 h = __float2bfloat16(v);
        __nv_bfloat16 l = __float2bfloat16(v - __bfloat162float(h));
        size_t idx = (size_t)(n0 + ty + 8*i) * HD + k0 + tx;
        hi[idx] = h;
        lo[idx] = l;
    }
}

// ---------------------------------------------------------------------------
// mma.sync GEMM: C = A @ Bt^T + bias, bf16 2-term split.
// CTA 128x128, K-chunk 32, 8 warps (2x4), warp tile 64x32.
// Output: either fp32 Cf, or split-bf16 (Chi, Clo).
// ---------------------------------------------------------------------------
#define KC 32
#define PITCHB 80
#define TILE_BYTES (128 * PITCHB)
#define STAGE_BYTES (4 * TILE_BYTES)
#define GEMM_SMEM (2 * STAGE_BYTES)     // 81920

__global__ __launch_bounds__(256, 1) void gemm_mma_kernel(
    const __nv_bfloat16* __restrict__ Ahi, const __nv_bfloat16* __restrict__ Alo,
    const __nv_bfloat16* __restrict__ Bhi, const __nv_bfloat16* __restrict__ Blo,
    const float* __restrict__ bias, float* __restrict__ Cf,
    __nv_bfloat16* __restrict__ Chi, __nv_bfloat16* __restrict__ Clo)
{
    extern __shared__ __align__(128) char smem[];
    const uint32_t sbase = smem_to_u32(smem);
    const int tid  = threadIdx.x;
    const int wid  = tid >> 5;
    const int lane = tid & 31;
    const int bm = blockIdx.y * 128;
    const int bn = blockIdx.x * 128;
    const int wm = (wid >> 2) * 64;
    const int wn = (wid & 3) * 32;

    float acc[4][4][4];
    #pragma unroll
    for (int mt = 0; mt < 4; mt++)
        #pragma unroll
        for (int nt = 0; nt < 4; nt++)
            #pragma unroll
            for (int i = 0; i < 4; i++) acc[mt][nt][i] = 0.f;

    const int lr = tid >> 2;
    const int lc = tid & 3;

    {
        const uint32_t sb = sbase;
        #pragma unroll
        for (int i = 0; i < 2; i++) {
            int r = lr + i * 64;
            uint32_t off = (uint32_t)r * PITCHB + lc * 16;
            size_t ga = (size_t)(bm + r) * HD + lc * 8;
            size_t gb = (size_t)(bn + r) * HD + lc * 8;
            cp_async16(sb + 0*TILE_BYTES + off, Ahi + ga);
            cp_async16(sb + 1*TILE_BYTES + off, Alo + ga);
            cp_async16(sb + 2*TILE_BYTES + off, Bhi + gb);
            cp_async16(sb + 3*TILE_BYTES + off, Blo + gb);
        }
        CP_COMMIT();
    }

    const int r8 = lane & 7;
    const int g  = lane >> 3;
    const uint32_t a_row_add  = (uint32_t)(r8 + ((g & 1) ? 8 : 0)) * PITCHB + ((g & 2) ? 16 : 0);
    const uint32_t b_row_add  = (uint32_t)(r8 + ((g >= 2) ? 8 : 0)) * PITCHB + ((g & 1) ? 16 : 0);

    for (int t = 0; t < HD / KC; t++) {
        if (t + 1 < HD / KC) {
            const int k0 = (t + 1) * KC;
            const uint32_t sb = sbase + ((t + 1) & 1) * STAGE_BYTES;
            #pragma unroll
            for (int i = 0; i < 2; i++) {
                int r = lr + i * 64;
                uint32_t off = (uint32_t)r * PITCHB + lc * 16;
                size_t ga = (size_t)(bm + r) * HD + k0 + lc * 8;
                size_t gb = (size_t)(bn + r) * HD + k0 + lc * 8;
                cp_async16(sb + 0*TILE_BYTES + off, Ahi + ga);
                cp_async16(sb + 1*TILE_BYTES + off, Alo + ga);
                cp_async16(sb + 2*TILE_BYTES + off, Bhi + gb);
                cp_async16(sb + 3*TILE_BYTES + off, Blo + gb);
            }
            CP_COMMIT();
            CP_WAIT(1);
        } else {
            CP_WAIT(0);
        }
        __syncthreads();

        const uint32_t sb = sbase + (t & 1) * STAGE_BYTES;
        #pragma unroll
        for (int ks = 0; ks < 2; ks++) {
            uint32_t ah[4][4], al[4][4], bh[2][4], bl[2][4];
            #pragma unroll
            for (int mt = 0; mt < 4; mt++) {
                uint32_t addr = sb + (uint32_t)(wm + mt * 16) * PITCHB + ks * 32 + a_row_add;
                ldsm_x4(ah[mt][0], ah[mt][1], ah[mt][2], ah[mt][3], addr + 0*TILE_BYTES);
                ldsm_x4(al[mt][0], al[mt][1], al[mt][2], al[mt][3], addr + 1*TILE_BYTES);
            }
            #pragma unroll
            for (int p = 0; p < 2; p++) {
                uint32_t addr = sb + (uint32_t)(wn + p * 16) * PITCHB + ks * 32 + b_row_add;
                ldsm_x4(bh[p][0], bh[p][1], bh[p][2], bh[p][3], addr + 2*TILE_BYTES);
                ldsm_x4(bl[p][0], bl[p][1], bl[p][2], bl[p][3], addr + 3*TILE_BYTES);
            }
            #pragma unroll
            for (int mt = 0; mt < 4; mt++) {
                #pragma unroll
                for (int nt = 0; nt < 4; nt++) {
                    uint32_t bh0 = bh[nt >> 1][(nt & 1) * 2 + 0];
                    uint32_t bh1 = bh[nt >> 1][(nt & 1) * 2 + 1];
                    uint32_t bl0 = bl[nt >> 1][(nt & 1) * 2 + 0];
                    uint32_t bl1 = bl[nt >> 1][(nt & 1) * 2 + 1];
                    mma_bf16(acc[mt][nt], ah[mt], bh0, bh1);
                    mma_bf16(acc[mt][nt], ah[mt], bl0, bl1);
                    mma_bf16(acc[mt][nt], al[mt], bh0, bh1);
                }
            }
        }
        __syncthreads();
    }

    const int er = lane >> 2;
    const int ec = (lane & 3) * 2;
    #pragma unroll
    for (int mt = 0; mt < 4; mt++) {
        #pragma unroll
        for (int nt = 0; nt < 4; nt++) {
            int row = bm + wm + mt * 16 + er;
            int col = bn + wn + nt * 8 + ec;
            float b0 = bias[col], b1 = bias[col + 1];
            float v0 = acc[mt][nt][0] + b0, v1 = acc[mt][nt][1] + b1;
            float v2 = acc[mt][nt][2] + b0, v3 = acc[mt][nt][3] + b1;
            if (Cf) {
                *(float2*)&Cf[(size_t)row * HD + col] = make_float2(v0, v1);
                *(float2*)&Cf[(size_t)(row + 8) * HD + col] = make_float2(v2, v3);
            } else {
                uint32_t h, l;
                split_pack(v0, v1, h, l);
                *(uint32_t*)&Chi[(size_t)row * HD + col] = h;
                *(uint32_t*)&Clo[(size_t)row * HD + col] = l;
                split_pack(v2, v3, h, l);
                *(uint32_t*)&Chi[(size_t)(row + 8) * HD + col] = h;
                *(uint32_t*)&Clo[(size_t)(row + 8) * HD + col] = l;
            }
        }
    }
}

// ---------------------------------------------------------------------------
// Tensor-core flash attention, split-bf16 for QK^T and P·V.
// CTA: 128 q-rows x one head. Warp: 16 rows x full key chunk (64).
// K chunk 64, cp.async double-buffered. Q held in registers as A-fragments.
// ---------------------------------------------------------------------------
#define VP 272                    // smem pitch bytes (256 data + 16 pad)
#define KTB (64 * VP)             // 17408 per tensor tile
#define STB (4 * KTB)             // 69632 per stage (Khi,Klo,Vhi,Vlo)
#define ATTN_SMEM (2 * STB)       // 139264
#define QHI_OFF 0
#define QLO_OFF (128 * VP)        // 34816 (Q staged in stage-0 area)

__global__ __launch_bounds__(256, 1) void attn_mma_kernel(
    const __nv_bfloat16* __restrict__ Qhi, const __nv_bfloat16* __restrict__ Qlo,
    const __nv_bfloat16* __restrict__ Khi, const __nv_bfloat16* __restrict__ Klo,
    const __nv_bfloat16* __restrict__ Vhi, const __nv_bfloat16* __restrict__ Vlo,
    const int* __restrict__ mask,
    __nv_bfloat16* __restrict__ Ahi, __nv_bfloat16* __restrict__ Alo)
{
    extern __shared__ __align__(128) char smem[];
    const uint32_t sbase = smem_to_u32(smem);
    const int tid  = threadIdx.x;
    const int wid  = tid >> 5;
    const int lane = tid & 31;
    const int q0 = blockIdx.x * 128;
    const int h  = blockIdx.y;
    const int b  = blockIdx.z;
    const int hc = h * DH;

    const int r8 = lane & 7;
    const int g  = lane >> 3;
    // A-operand ldsm addressing (rows 0-7/8-15 x k halves)
    const uint32_t a_add = (uint32_t)(r8 + ((g & 1) ? 8 : 0)) * VP + ((g & 2) ? 16 : 0);
    // B-operand (K, non-trans): rows = key
    const uint32_t b_add = (uint32_t)(r8 + ((g >= 2) ? 8 : 0)) * VP + ((g & 1) ? 16 : 0);
    // B-operand (V, trans): rows = key, cols = d
    const uint32_t v_add = (uint32_t)(r8 + ((g & 1) ? 8 : 0)) * VP + ((g >> 1) ? 16 : 0);

    // ---- stage Q tile (128 x 128 d, hi+lo) and load A-fragments ----
    {
        #pragma unroll
        for (int i = 0; i < 8; i++) {
            int lin = i * 256 + tid;       // 2048 16B-chunks
            int r = lin >> 4, c = lin & 15;
            size_t gq = (size_t)(b * SQ + q0 + r) * HD + hc + c * 8;
            cp_async16(sbase + QHI_OFF + (uint32_t)r * VP + c * 16, Qhi + gq);
            cp_async16(sbase + QLO_OFF + (uint32_t)r * VP + c * 16, Qlo + gq);
        }
        CP_COMMIT();
        CP_WAIT(0);
        __syncthreads();
    }

    uint32_t qh[8][4], ql[8][4];
    #pragma unroll
    for (int ks = 0; ks < 8; ks++) {
        uint32_t addr = (uint32_t)(16 * wid) * VP + ks * 32 + a_add;
        ldsm_x4(qh[ks][0], qh[ks][1], qh[ks][2], qh[ks][3], sbase + QHI_OFF + addr);
        ldsm_x4(ql[ks][0], ql[ks][1], ql[ks][2], ql[ks][3], sbase + QLO_OFF + addr);
    }
    __syncthreads();   // Q staging area free for K/V stage 0

    // ---- prefetch chunk 0 ----
    #define LOAD_CHUNK(T, STAGE) do {                                           \
        const uint32_t _sb = sbase + (STAGE) * STB;                             \
        _Pragma("unroll")                                                       \
        for (int _i = 0; _i < 4; _i++) {                                        \
            int _lin = _i * 256 + tid;                                          \
            int _r = _lin >> 4, _c = _lin & 15;                                 \
            size_t _gk = (size_t)(b * SQ + (T) * 64 + _r) * HD + hc + _c * 8;   \
            uint32_t _off = (uint32_t)_r * VP + _c * 16;                        \
            cp_async16(_sb + 0*KTB + _off, Khi + _gk);                          \
            cp_async16(_sb + 1*KTB + _off, Klo + _gk);                          \
            cp_async16(_sb + 2*KTB + _off, Vhi + _gk);                          \
            cp_async16(_sb + 3*KTB + _off, Vlo + _gk);                          \
        }                                                                       \
        CP_COMMIT();                                                            \
    } while (0)

    LOAD_CHUNK(0, 0);

    float m0 = -1e30f, m1 = -1e30f, l0 = 0.f, l1 = 0.f;
    float o[16][4];
    #pragma unroll
    for (int nt = 0; nt < 16; nt++)
        #pragma unroll
        for (int i = 0; i < 4; i++) o[nt][i] = 0.f;

    const float scale = 0.08838834764831845f;   // 1/sqrt(128)
    const int row0 = q0 + 16 * wid + (lane >> 2);
    const int c2 = (lane & 3) * 2;
    const int* mrow0 = mask + ((size_t)b * SQ + row0) * SQ;
    const int* mrow1 = mrow0 + 8 * SQ;

    for (int t = 0; t < SQ / 64; t++) {
        if (t + 1 < SQ / 64) { LOAD_CHUNK(t + 1, (t + 1) & 1); CP_WAIT(1); }
        else CP_WAIT(0);
        __syncthreads();

        const uint32_t sb = sbase + (t & 1) * STB;

        // ---- S = Q K^T (split) ----
        float s[8][4];
        #pragma unroll
        for (int j = 0; j < 8; j++)
            #pragma unroll
            for (int i = 0; i < 4; i++) s[j][i] = 0.f;

        #pragma unroll
        for (int ks = 0; ks < 8; ks++) {
            #pragma unroll
            for (int p = 0; p < 4; p++) {
                uint32_t kh[4], kl[4];
                uint32_t addr = sb + (uint32_t)(16 * p) * VP + ks * 32 + b_add;
                ldsm_x4(kh[0], kh[1], kh[2], kh[3], addr + 0*KTB);
                ldsm_x4(kl[0], kl[1], kl[2], kl[3], addr + 1*KTB);
                mma_bf16(s[2*p],   qh[ks], kh[0], kh[1]);
                mma_bf16(s[2*p],   qh[ks], kl[0], kl[1]);
                mma_bf16(s[2*p],   ql[ks], kh[0], kh[1]);
                mma_bf16(s[2*p+1], qh[ks], kh[2], kh[3]);
                mma_bf16(s[2*p+1], qh[ks], kl[2], kl[3]);
                mma_bf16(s[2*p+1], ql[ks], kh[2], kh[3]);
            }
        }

        // ---- mask + scale + online softmax ----
        const int k0 = t * 64;
        float mx0 = -1e30f, mx1 = -1e30f;
        #pragma unroll
        for (int j = 0; j < 8; j++) {
            int2 mm0 = *(const int2*)&mrow0[k0 + 8*j + c2];
            int2 mm1 = *(const int2*)&mrow1[k0 + 8*j + c2];
            s[j][0] = mm0.x ? s[j][0] * scale : -1e30f;
            s[j][1] = mm0.y ? s[j][1] * scale : -1e30f;
            s[j][2] = mm1.x ? s[j][2] * scale : -1e30f;
            s[j][3] = mm1.y ? s[j][3] * scale : -1e30f;
            mx0 = fmaxf(mx0, fmaxf(s[j][0], s[j][1]));
            mx1 = fmaxf(mx1, fmaxf(s[j][2], s[j][3]));
        }
        mx0 = fmaxf(mx0, __shfl_xor_sync(0xffffffffu, mx0, 1));
        mx0 = fmaxf(mx0, __shfl_xor_sync(0xffffffffu, mx0, 2));
        mx1 = fmaxf(mx1, __shfl_xor_sync(0xffffffffu, mx1, 1));
        mx1 = fmaxf(mx1, __shfl_xor_sync(0xffffffffu, mx1, 2));

        float mn0 = fmaxf(m0, mx0), mn1 = fmaxf(m1, mx1);
        float corr0 = __expf(m0 - mn0), corr1 = __expf(m1 - mn1);
        m0 = mn0; m1 = mn1;

        float ps0 = 0.f, ps1 = 0.f;
        #pragma unroll
        for (int j = 0; j < 8; j++) {
            s[j][0] = __expf(s[j][0] - m0);
            s[j][1] = __expf(s[j][1] - m0);
            s[j][2] = __expf(s[j][2] - m1);
            s[j][3] = __expf(s[j][3] - m1);
            ps0 += s[j][0] + s[j][1];
            ps1 += s[j][2] + s[j][3];
        }
        ps0 += __shfl_xor_sync(0xffffffffu, ps0, 1);
        ps0 += __shfl_xor_sync(0xffffffffu, ps0, 2);
        ps1 += __shfl_xor_sync(0xffffffffu, ps1, 1);
        ps1 += __shfl_xor_sync(0xffffffffu, ps1, 2);
        l0 = l0 * corr0 + ps0;
        l1 = l1 * corr1 + ps1;

        #pragma unroll
        for (int nt = 0; nt < 16; nt++) {
            o[nt][0] *= corr0; o[nt][1] *= corr0;
            o[nt][2] *= corr1; o[nt][3] *= corr1;
        }

        // ---- O += P V (split) ----
        #pragma unroll
        for (int ks = 0; ks < 4; ks++) {
            uint32_t ph[4], pl[4];
            split_pack(s[2*ks][0],   s[2*ks][1],   ph[0], pl[0]);
            split_pack(s[2*ks][2],   s[2*ks][3],   ph[1], pl[1]);
            split_pack(s[2*ks+1][0], s[2*ks+1][1], ph[2], pl[2]);
            split_pack(s[2*ks+1][2], s[2*ks+1][3], ph[3], pl[3]);
            #pragma unroll
            for (int dp = 0; dp < 8; dp++) {
                uint32_t vh[4], vl[4];
                uint32_t addr = sb + (uint32_t)(16 * ks) * VP + dp * 32 + v_add;
                ldsm_x4_t(vh[0], vh[1], vh[2], vh[3], addr + 2*KTB);
                ldsm_x4_t(vl[0], vl[1], vl[2], vl[3], addr + 3*KTB);
                mma_bf16(o[2*dp],   ph, vh[0], vh[1]);
                mma_bf16(o[2*dp],   ph, vl[0], vl[1]);
                mma_bf16(o[2*dp],   pl, vh[0], vh[1]);
                mma_bf16(o[2*dp+1], ph, vh[2], vh[3]);
                mma_bf16(o[2*dp+1], ph, vl[2], vl[3]);
                mma_bf16(o[2*dp+1], pl, vh[2], vh[3]);
            }
        }
        __syncthreads();
    }

    // ---- epilogue: normalize and store split bf16 ----
    const float inv0 = 1.f / l0, inv1 = 1.f / l1;
    const size_t ob0 = (size_t)(b * SQ + row0) * HD + hc;
    const size_t ob1 = ob0 + (size_t)8 * HD;
    #pragma unroll
    for (int nt = 0; nt < 16; nt++) {
        int col = 8 * nt + c2;
        uint32_t hh, ll;
        split_pack(o[nt][0] * inv0, o[nt][1] * inv0, hh, ll);
        *(uint32_t*)&Ahi[ob0 + col] = hh;
        *(uint32_t*)&Alo[ob0 + col] = ll;
        split_pack(o[nt][2] * inv1, o[nt][3] * inv1, hh, ll);
        *(uint32_t*)&Ahi[ob1 + col] = hh;
        *(uint32_t*)&Alo[ob1 + col] = ll;
    }
}

// ---------------------------------------------------------------------------

extern "C" void kernel_launch(void* const* d_in, const int* in_sizes, int n_in,
                              void* d_out, int out_size)
{
    const float* X   = (const float*)d_in[0];
    const int*   msk = (const int*)  d_in[1];
    const float* Wq  = (const float*)d_in[2];
    const float* bq  = (const float*)d_in[3];
    const float* Wk  = (const float*)d_in[4];
    const float* bk  = (const float*)d_in[5];
    const float* Wv  = (const float*)d_in[6];
    const float* bv  = (const float*)d_in[7];
    const float* Wo  = (const float*)d_in[8];
    const float* bo  = (const float*)d_in[9];
    float* out = (float*)d_out;

    __nv_bfloat16 *Qhi, *Qlo, *Khi, *Klo, *Vhi, *Vlo, *Ahi, *Alo, *Xhi, *Xlo, *Wthi, *Wtlo;
    cudaGetSymbolAddress((void**)&Qhi, g_Qhi);
    cudaGetSymbolAddress((void**)&Qlo, g_Qlo);
    cudaGetSymbolAddress((void**)&Khi, g_Khi);
    cudaGetSymbolAddress((void**)&Klo, g_Klo);
    cudaGetSymbolAddress((void**)&Vhi, g_Vhi);
    cudaGetSymbolAddress((void**)&Vlo, g_Vlo);
    cudaGetSymbolAddress((void**)&Ahi, g_Ahi);
    cudaGetSymbolAddress((void**)&Alo, g_Alo);
    cudaGetSymbolAddress((void**)&Xhi, g_Xhi);
    cudaGetSymbolAddress((void**)&Xlo, g_Xlo);
    cudaGetSymbolAddress((void**)&Wthi, g_Wthi);
    cudaGetSymbolAddress((void**)&Wtlo, g_Wtlo);

    const size_t WSZ = (size_t)HD * HD;
    const int n4 = MR * HD / 4;

    cudaFuncSetAttribute(gemm_mma_kernel,
                         cudaFuncAttributeMaxDynamicSharedMemorySize, GEMM_SMEM);
    cudaFuncSetAttribute(attn_mma_kernel,
                         cudaFuncAttributeMaxDynamicSharedMemorySize, ATTN_SMEM);

    // 1. bf16 hi/lo splits of X and transposed weights
    cvt_split_kernel<<<n4 / 256, 256>>>((const float4*)X, Xhi, Xlo, n4);
    dim3 wg(HD / 32, HD / 32), wb(32, 8);
    cvt_wt_kernel<<<wg, wb>>>(Wq, Wthi + 0*WSZ, Wtlo + 0*WSZ);
    cvt_wt_kernel<<<wg, wb>>>(Wk, Wthi + 1*WSZ, Wtlo + 1*WSZ);
    cvt_wt_kernel<<<wg, wb>>>(Wv, Wthi + 2*WSZ, Wtlo + 2*WSZ);
    cvt_wt_kernel<<<wg, wb>>>(Wo, Wthi + 3*WSZ, Wtlo + 3*WSZ);

    // 2. Q/K/V projections -> split-bf16 outputs directly
    dim3 gg(HD / 128, MR / 128);   // (16, 32)
    gemm_mma_kernel<<<gg, 256, GEMM_SMEM>>>(Xhi, Xlo, Wthi + 0*WSZ, Wtlo + 0*WSZ, bq,
                                            nullptr, Qhi, Qlo);
    gemm_mma_kernel<<<gg, 256, GEMM_SMEM>>>(Xhi, Xlo, Wthi + 1*WSZ, Wtlo + 1*WSZ, bk,
                                            nullptr, Khi, Klo);
    gemm_mma_kernel<<<gg, 256, GEMM_SMEM>>>(Xhi, Xlo, Wthi + 2*WSZ, Wtlo + 2*WSZ, bv,
                                            nullptr, Vhi, Vlo);

    // 3. tensor-core flash attention -> split-bf16 A
    dim3 ga(SQ / 128, NH, BB);     // (16, 16, 2)
    attn_mma_kernel<<<ga, 256, ATTN_SMEM>>>(Qhi, Qlo, Khi, Klo, Vhi, Vlo, msk, Ahi, Alo);

    // 4. output projection -> fp32 out
    gemm_mma_kernel<<<gg, 256, GEMM_SMEM>>>(Ahi, Alo, Wthi + 3*WSZ, Wtlo + 3*WSZ, bo,
                                            out, nullptr, nullptr);
}

// round 7
// speedup vs baseline: 7.0536x; 1.1790x over previous
#include <cuda_runtime.h>
#include <cuda_bf16.h>
#include <cstdint>

#define HD 2048
#define NH 16
#define DH 128
#define BB 2
#define SQ 2048
#define MR (BB*SQ)   // 4096 rows

// ---------------------------------------------------------------------------
// Scratch (device globals; no allocations allowed)
// ---------------------------------------------------------------------------
__device__ __nv_bfloat16 g_Qhi[(size_t)MR*HD];
__device__ __nv_bfloat16 g_Qlo[(size_t)MR*HD];
__device__ __nv_bfloat16 g_Khi[(size_t)MR*HD];
__device__ __nv_bfloat16 g_Klo[(size_t)MR*HD];
__device__ __nv_bfloat16 g_Vhi[(size_t)MR*HD];
__device__ __nv_bfloat16 g_Vlo[(size_t)MR*HD];
__device__ __nv_bfloat16 g_Ahi[(size_t)MR*HD];
__device__ __nv_bfloat16 g_Alo[(size_t)MR*HD];
__device__ __nv_bfloat16 g_Xhi[(size_t)MR*HD];
__device__ __nv_bfloat16 g_Xlo[(size_t)MR*HD];
__device__ __nv_bfloat16 g_Wthi[4][(size_t)HD*HD];   // transposed: [n][k]; Q,K,V contiguous
__device__ __nv_bfloat16 g_Wtlo[4][(size_t)HD*HD];

// ---------------------------------------------------------------------------
// PTX helpers (compute_103-safe: mma.sync / ldmatrix / cp.async only)
// ---------------------------------------------------------------------------
__device__ __forceinline__ uint32_t smem_to_u32(const void* p) {
    uint32_t a;
    asm("{ .reg .u64 t; cvta.to.shared.u64 t, %1; cvt.u32.u64 %0, t; }"
        : "=r"(a) : "l"(p));
    return a;
}
__device__ __forceinline__ void cp_async16(uint32_t s, const void* g) {
    asm volatile("cp.async.cg.shared.global [%0], [%1], 16;" :: "r"(s), "l"(g));
}
#define CP_COMMIT() asm volatile("cp.async.commit_group;" ::: "memory")
#define CP_WAIT(n)  asm volatile("cp.async.wait_group %0;" :: "n"(n) : "memory")

__device__ __forceinline__ void ldsm_x4(uint32_t& r0, uint32_t& r1,
                                        uint32_t& r2, uint32_t& r3, uint32_t addr) {
    asm volatile("ldmatrix.sync.aligned.m8n8.x4.shared.b16 {%0,%1,%2,%3}, [%4];"
        : "=r"(r0), "=r"(r1), "=r"(r2), "=r"(r3) : "r"(addr));
}
__device__ __forceinline__ void ldsm_x4_t(uint32_t& r0, uint32_t& r1,
                                          uint32_t& r2, uint32_t& r3, uint32_t addr) {
    asm volatile("ldmatrix.sync.aligned.m8n8.x4.trans.shared.b16 {%0,%1,%2,%3}, [%4];"
        : "=r"(r0), "=r"(r1), "=r"(r2), "=r"(r3) : "r"(addr));
}
__device__ __forceinline__ void mma_bf16(float* c, const uint32_t* a,
                                         uint32_t b0, uint32_t b1) {
    asm volatile(
        "mma.sync.aligned.m16n8k16.row.col.f32.bf16.bf16.f32 "
        "{%0,%1,%2,%3}, {%4,%5,%6,%7}, {%8,%9}, {%0,%1,%2,%3};"
        : "+f"(c[0]), "+f"(c[1]), "+f"(c[2]), "+f"(c[3])
        : "r"(a[0]), "r"(a[1]), "r"(a[2]), "r"(a[3]), "r"(b0), "r"(b1));
}
__device__ __forceinline__ uint32_t pack_bf2(__nv_bfloat16 a, __nv_bfloat16 b) {
    __nv_bfloat162 t(a, b);
    return *(uint32_t*)&t;
}
__device__ __forceinline__ void split_pack(float x, float y, uint32_t& hi, uint32_t& lo) {
    __nv_bfloat16 hx = __float2bfloat16(x);
    __nv_bfloat16 hy = __float2bfloat16(y);
    __nv_bfloat16 lx = __float2bfloat16(x - __bfloat162float(hx));
    __nv_bfloat16 ly = __float2bfloat16(y - __bfloat162float(hy));
    hi = pack_bf2(hx, hy);
    lo = pack_bf2(lx, ly);
}

// ---------------------------------------------------------------------------
// Conversion kernels
// ---------------------------------------------------------------------------
__global__ __launch_bounds__(256) void cvt_split_kernel(
    const float4* __restrict__ in, __nv_bfloat16* __restrict__ hi,
    __nv_bfloat16* __restrict__ lo, int n4)
{
    int i = blockIdx.x * 256 + threadIdx.x;
    if (i >= n4) return;
    float4 v = in[i];
    float f[4] = {v.x, v.y, v.z, v.w};
    #pragma unroll
    for (int p = 0; p < 2; p++) {
        uint32_t h, l;
        split_pack(f[2*p+0], f[2*p+1], h, l);
        ((uint32_t*)hi)[2*i+p] = h;
        ((uint32_t*)lo)[2*i+p] = l;
    }
}

// Batched: W[K,N] fp32 -> Wt[n][k] bf16 hi/lo. blockIdx.z selects weight.
__global__ __launch_bounds__(256) void cvt_wt_kernel(
    const float* __restrict__ W0, const float* __restrict__ W1,
    const float* __restrict__ W2, const float* __restrict__ W3,
    __nv_bfloat16* __restrict__ hib, __nv_bfloat16* __restrict__ lob)
{
    __shared__ float tile[32][33];
    const int z = blockIdx.z;
    const float* W = (z == 0) ? W0 : (z == 1) ? W1 : (z == 2) ? W2 : W3;
    __nv_bfloat16* hi = hib + (size_t)z * HD * HD;
    __nv_bfloat16* lo = lob + (size_t)z * HD * HD;
    const int n0 = blockIdx.x * 32, k0 = blockIdx.y * 32;
    const int tx = threadIdx.x, ty = threadIdx.y;   // block (32, 8)
    #pragma unroll
    for (int i = 0; i < 4; i++)
        tile[ty + 8*i][tx] = W[(size_t)(k0 + ty + 8*i) * HD + n0 + tx];
    __syncthreads();
    #pragma unroll
    for (int i = 0; i < 4; i++) {
        float v = tile[tx][ty + 8*i];
        __nv_bfloat16 h = __float2bfloat16(v);
        __nv_bfloat16 l = __float2bfloat16(v - __bfloat162float(h));
        size_t idx = (size_t)(n0 + ty + 8*i) * HD + k0 + tx;
        hi[idx] = h;
        lo[idx] = l;
    }
}

// ---------------------------------------------------------------------------
// mma.sync GEMM, bf16 2-term split, CTA 128x128, KC=32, 8 warps (2x4).
// MODE 0: fused QKV — B rows span concatenated [Wq;Wk;Wv] (6144), outputs
//         split-bf16 into Q/K/V selected per CTA. grid.x = 48.
// MODE 1: O-projection — fp32 output + bias. grid.x = 16.
// 2 CTAs/SM (160KB smem total) for latency hiding.
// ---------------------------------------------------------------------------
#define KC 32
#define PITCHB 80
#define TILE_BYTES (128 * PITCHB)
#define STAGE_BYTES (4 * TILE_BYTES)
#define GEMM_SMEM (2 * STAGE_BYTES)     // 81920

template<int MODE>
__global__ __launch_bounds__(256, 2) void gemm_mma_kernel(
    const __nv_bfloat16* __restrict__ Ahi, const __nv_bfloat16* __restrict__ Alo,
    const __nv_bfloat16* __restrict__ Bhi, const __nv_bfloat16* __restrict__ Blo,
    const float* __restrict__ b0, const float* __restrict__ b1,
    const float* __restrict__ b2,
    __nv_bfloat16* __restrict__ o0h, __nv_bfloat16* __restrict__ o0l,
    __nv_bfloat16* __restrict__ o1h, __nv_bfloat16* __restrict__ o1l,
    __nv_bfloat16* __restrict__ o2h, __nv_bfloat16* __restrict__ o2l,
    float* __restrict__ Cf)
{
    extern __shared__ __align__(128) char smem[];
    const uint32_t sbase = smem_to_u32(smem);
    const int tid  = threadIdx.x;
    const int wid  = tid >> 5;
    const int lane = tid & 31;
    const int bm = blockIdx.y * 128;
    const int bn = blockIdx.x * 128;    // index into (possibly concatenated) N
    const int wm = (wid >> 2) * 64;
    const int wn = (wid & 3) * 32;

    float acc[4][4][4];
    #pragma unroll
    for (int mt = 0; mt < 4; mt++)
        #pragma unroll
        for (int nt = 0; nt < 4; nt++)
            #pragma unroll
            for (int i = 0; i < 4; i++) acc[mt][nt][i] = 0.f;

    const int lr = tid >> 2;
    const int lc = tid & 3;

    {
        const uint32_t sb = sbase;
        #pragma unroll
        for (int i = 0; i < 2; i++) {
            int r = lr + i * 64;
            uint32_t off = (uint32_t)r * PITCHB + lc * 16;
            size_t ga = (size_t)(bm + r) * HD + lc * 8;
            size_t gb = (size_t)(bn + r) * HD + lc * 8;
            cp_async16(sb + 0*TILE_BYTES + off, Ahi + ga);
            cp_async16(sb + 1*TILE_BYTES + off, Alo + ga);
            cp_async16(sb + 2*TILE_BYTES + off, Bhi + gb);
            cp_async16(sb + 3*TILE_BYTES + off, Blo + gb);
        }
        CP_COMMIT();
    }

    const int r8 = lane & 7;
    const int g  = lane >> 3;
    const uint32_t a_row_add = (uint32_t)(r8 + ((g & 1) ? 8 : 0)) * PITCHB + ((g & 2) ? 16 : 0);
    const uint32_t b_row_add = (uint32_t)(r8 + ((g >= 2) ? 8 : 0)) * PITCHB + ((g & 1) ? 16 : 0);

    for (int t = 0; t < HD / KC; t++) {
        if (t + 1 < HD / KC) {
            const int k0 = (t + 1) * KC;
            const uint32_t sb = sbase + ((t + 1) & 1) * STAGE_BYTES;
            #pragma unroll
            for (int i = 0; i < 2; i++) {
                int r = lr + i * 64;
                uint32_t off = (uint32_t)r * PITCHB + lc * 16;
                size_t ga = (size_t)(bm + r) * HD + k0 + lc * 8;
                size_t gb = (size_t)(bn + r) * HD + k0 + lc * 8;
                cp_async16(sb + 0*TILE_BYTES + off, Ahi + ga);
                cp_async16(sb + 1*TILE_BYTES + off, Alo + ga);
                cp_async16(sb + 2*TILE_BYTES + off, Bhi + gb);
                cp_async16(sb + 3*TILE_BYTES + off, Blo + gb);
            }
            CP_COMMIT();
            CP_WAIT(1);
        } else {
            CP_WAIT(0);
        }
        __syncthreads();

        const uint32_t sb = sbase + (t & 1) * STAGE_BYTES;
        #pragma unroll
        for (int ks = 0; ks < 2; ks++) {
            // B fragments first (kept live across all mt)
            uint32_t bh[2][4], bl[2][4];
            #pragma unroll
            for (int p = 0; p < 2; p++) {
                uint32_t addr = sb + (uint32_t)(wn + p * 16) * PITCHB + ks * 32 + b_row_add;
                ldsm_x4(bh[p][0], bh[p][1], bh[p][2], bh[p][3], addr + 2*TILE_BYTES);
                ldsm_x4(bl[p][0], bl[p][1], bl[p][2], bl[p][3], addr + 3*TILE_BYTES);
            }
            #pragma unroll
            for (int mt = 0; mt < 4; mt++) {
                uint32_t ah[4], al[4];
                uint32_t addr = sb + (uint32_t)(wm + mt * 16) * PITCHB + ks * 32 + a_row_add;
                ldsm_x4(ah[0], ah[1], ah[2], ah[3], addr + 0*TILE_BYTES);
                ldsm_x4(al[0], al[1], al[2], al[3], addr + 1*TILE_BYTES);
                #pragma unroll
                for (int nt = 0; nt < 4; nt++) {
                    uint32_t bh0 = bh[nt >> 1][(nt & 1) * 2 + 0];
                    uint32_t bh1 = bh[nt >> 1][(nt & 1) * 2 + 1];
                    uint32_t bl0 = bl[nt >> 1][(nt & 1) * 2 + 0];
                    uint32_t bl1 = bl[nt >> 1][(nt & 1) * 2 + 1];
                    mma_bf16(acc[mt][nt], ah, bh0, bh1);
                    mma_bf16(acc[mt][nt], ah, bl0, bl1);
                    mma_bf16(acc[mt][nt], al, bh0, bh1);
                }
            }
        }
        __syncthreads();
    }

    const int er = lane >> 2;
    const int ec = (lane & 3) * 2;

    if (MODE == 0) {
        const int w  = bn >> 11;            // which weight (0=Q,1=K,2=V)
        const int ln = (bn & 2047) + wn;    // local col base
        const float* bias = (w == 0) ? b0 : (w == 1) ? b1 : b2;
        __nv_bfloat16* oh = (w == 0) ? o0h : (w == 1) ? o1h : o2h;
        __nv_bfloat16* ol = (w == 0) ? o0l : (w == 1) ? o1l : o2l;
        #pragma unroll
        for (int mt = 0; mt < 4; mt++) {
            #pragma unroll
            for (int nt = 0; nt < 4; nt++) {
                int row = bm + wm + mt * 16 + er;
                int col = ln + nt * 8 + ec;
                float bb0 = bias[col], bb1 = bias[col + 1];
                uint32_t h, l;
                split_pack(acc[mt][nt][0] + bb0, acc[mt][nt][1] + bb1, h, l);
                *(uint32_t*)&oh[(size_t)row * HD + col] = h;
                *(uint32_t*)&ol[(size_t)row * HD + col] = l;
                split_pack(acc[mt][nt][2] + bb0, acc[mt][nt][3] + bb1, h, l);
                *(uint32_t*)&oh[(size_t)(row + 8) * HD + col] = h;
                *(uint32_t*)&ol[(size_t)(row + 8) * HD + col] = l;
            }
        }
    } else {
        #pragma unroll
        for (int mt = 0; mt < 4; mt++) {
            #pragma unroll
            for (int nt = 0; nt < 4; nt++) {
                int row = bm + wm + mt * 16 + er;
                int col = bn + wn + nt * 8 + ec;
                float bb0 = b0[col], bb1 = b0[col + 1];
                *(float2*)&Cf[(size_t)row * HD + col] =
                    make_float2(acc[mt][nt][0] + bb0, acc[mt][nt][1] + bb1);
                *(float2*)&Cf[(size_t)(row + 8) * HD + col] =
                    make_float2(acc[mt][nt][2] + bb0, acc[mt][nt][3] + bb1);
            }
        }
    }
}

// ---------------------------------------------------------------------------
// Tensor-core flash attention, split-bf16 for QK^T and P·V. (unchanged)
// ---------------------------------------------------------------------------
#define VP 272
#define KTB (64 * VP)
#define STB (4 * KTB)
#define ATTN_SMEM (2 * STB)       // 139264
#define QHI_OFF 0
#define QLO_OFF (128 * VP)

__global__ __launch_bounds__(256, 1) void attn_mma_kernel(
    const __nv_bfloat16* __restrict__ Qhi, const __nv_bfloat16* __restrict__ Qlo,
    const __nv_bfloat16* __restrict__ Khi, const __nv_bfloat16* __restrict__ Klo,
    const __nv_bfloat16* __restrict__ Vhi, const __nv_bfloat16* __restrict__ Vlo,
    const int* __restrict__ mask,
    __nv_bfloat16* __restrict__ Ahi, __nv_bfloat16* __restrict__ Alo)
{
    extern __shared__ __align__(128) char smem[];
    const uint32_t sbase = smem_to_u32(smem);
    const int tid  = threadIdx.x;
    const int wid  = tid >> 5;
    const int lane = tid & 31;
    const int q0 = blockIdx.x * 128;
    const int h  = blockIdx.y;
    const int b  = blockIdx.z;
    const int hc = h * DH;

    const int r8 = lane & 7;
    const int g  = lane >> 3;
    const uint32_t a_add = (uint32_t)(r8 + ((g & 1) ? 8 : 0)) * VP + ((g & 2) ? 16 : 0);
    const uint32_t b_add = (uint32_t)(r8 + ((g >= 2) ? 8 : 0)) * VP + ((g & 1) ? 16 : 0);
    const uint32_t v_add = (uint32_t)(r8 + ((g & 1) ? 8 : 0)) * VP + ((g >> 1) ? 16 : 0);

    {
        #pragma unroll
        for (int i = 0; i < 8; i++) {
            int lin = i * 256 + tid;
            int r = lin >> 4, c = lin & 15;
            size_t gq = (size_t)(b * SQ + q0 + r) * HD + hc + c * 8;
            cp_async16(sbase + QHI_OFF + (uint32_t)r * VP + c * 16, Qhi + gq);
            cp_async16(sbase + QLO_OFF + (uint32_t)r * VP + c * 16, Qlo + gq);
        }
        CP_COMMIT();
        CP_WAIT(0);
        __syncthreads();
    }

    uint32_t qh[8][4], ql[8][4];
    #pragma unroll
    for (int ks = 0; ks < 8; ks++) {
        uint32_t addr = (uint32_t)(16 * wid) * VP + ks * 32 + a_add;
        ldsm_x4(qh[ks][0], qh[ks][1], qh[ks][2], qh[ks][3], sbase + QHI_OFF + addr);
        ldsm_x4(ql[ks][0], ql[ks][1], ql[ks][2], ql[ks][3], sbase + QLO_OFF + addr);
    }
    __syncthreads();

    #define LOAD_CHUNK(T, STAGE) do {                                           \
        const uint32_t _sb = sbase + (STAGE) * STB;                             \
        _Pragma("unroll")                                                       \
        for (int _i = 0; _i < 4; _i++) {                                        \
            int _lin = _i * 256 + tid;                                          \
            int _r = _lin >> 4, _c = _lin & 15;                                 \
            size_t _gk = (size_t)(b * SQ + (T) * 64 + _r) * HD + hc + _c * 8;   \
            uint32_t _off = (uint32_t)_r * VP + _c * 16;                        \
            cp_async16(_sb + 0*KTB + _off, Khi + _gk);                          \
            cp_async16(_sb + 1*KTB + _off, Klo + _gk);                          \
            cp_async16(_sb + 2*KTB + _off, Vhi + _gk);                          \
            cp_async16(_sb + 3*KTB + _off, Vlo + _gk);                          \
        }                                                                       \
        CP_COMMIT();                                                            \
    } while (0)

    LOAD_CHUNK(0, 0);

    float m0 = -1e30f, m1 = -1e30f, l0 = 0.f, l1 = 0.f;
    float o[16][4];
    #pragma unroll
    for (int nt = 0; nt < 16; nt++)
        #pragma unroll
        for (int i = 0; i < 4; i++) o[nt][i] = 0.f;

    const float scale = 0.08838834764831845f;
    const int row0 = q0 + 16 * wid + (lane >> 2);
    const int c2 = (lane & 3) * 2;
    const int* mrow0 = mask + ((size_t)b * SQ + row0) * SQ;
    const int* mrow1 = mrow0 + 8 * SQ;

    for (int t = 0; t < SQ / 64; t++) {
        if (t + 1 < SQ / 64) { LOAD_CHUNK(t + 1, (t + 1) & 1); CP_WAIT(1); }
        else CP_WAIT(0);
        __syncthreads();

        const uint32_t sb = sbase + (t & 1) * STB;

        float s[8][4];
        #pragma unroll
        for (int j = 0; j < 8; j++)
            #pragma unroll
            for (int i = 0; i < 4; i++) s[j][i] = 0.f;

        #pragma unroll
        for (int ks = 0; ks < 8; ks++) {
            #pragma unroll
            for (int p = 0; p < 4; p++) {
                uint32_t kh[4], kl[4];
                uint32_t addr = sb + (uint32_t)(16 * p) * VP + ks * 32 + b_add;
                ldsm_x4(kh[0], kh[1], kh[2], kh[3], addr + 0*KTB);
                ldsm_x4(kl[0], kl[1], kl[2], kl[3], addr + 1*KTB);
                mma_bf16(s[2*p],   qh[ks], kh[0], kh[1]);
                mma_bf16(s[2*p],   qh[ks], kl[0], kl[1]);
                mma_bf16(s[2*p],   ql[ks], kh[0], kh[1]);
                mma_bf16(s[2*p+1], qh[ks], kh[2], kh[3]);
                mma_bf16(s[2*p+1], qh[ks], kl[2], kl[3]);
                mma_bf16(s[2*p+1], ql[ks], kh[2], kh[3]);
            }
        }

        const int k0 = t * 64;
        float mx0 = -1e30f, mx1 = -1e30f;
        #pragma unroll
        for (int j = 0; j < 8; j++) {
            int2 mm0 = *(const int2*)&mrow0[k0 + 8*j + c2];
            int2 mm1 = *(const int2*)&mrow1[k0 + 8*j + c2];
            s[j][0] = mm0.x ? s[j][0] * scale : -1e30f;
            s[j][1] = mm0.y ? s[j][1] * scale : -1e30f;
            s[j][2] = mm1.x ? s[j][2] * scale : -1e30f;
            s[j][3] = mm1.y ? s[j][3] * scale : -1e30f;
            mx0 = fmaxf(mx0, fmaxf(s[j][0], s[j][1]));
            mx1 = fmaxf(mx1, fmaxf(s[j][2], s[j][3]));
        }
        mx0 = fmaxf(mx0, __shfl_xor_sync(0xffffffffu, mx0, 1));
        mx0 = fmaxf(mx0, __shfl_xor_sync(0xffffffffu, mx0, 2));
        mx1 = fmaxf(mx1, __shfl_xor_sync(0xffffffffu, mx1, 1));
        mx1 = fmaxf(mx1, __shfl_xor_sync(0xffffffffu, mx1, 2));

        float mn0 = fmaxf(m0, mx0), mn1 = fmaxf(m1, mx1);
        float corr0 = __expf(m0 - mn0), corr1 = __expf(m1 - mn1);
        m0 = mn0; m1 = mn1;

        float ps0 = 0.f, ps1 = 0.f;
        #pragma unroll
        for (int j = 0; j < 8; j++) {
            s[j][0] = __expf(s[j][0] - m0);
            s[j][1] = __expf(s[j][1] - m0);
            s[j][2] = __expf(s[j][2] - m1);
            s[j][3] = __expf(s[j][3] - m1);
            ps0 += s[j][0] + s[j][1];
            ps1 += s[j][2] + s[j][3];
        }
        ps0 += __shfl_xor_sync(0xffffffffu, ps0, 1);
        ps0 += __shfl_xor_sync(0xffffffffu, ps0, 2);
        ps1 += __shfl_xor_sync(0xffffffffu, ps1, 1);
        ps1 += __shfl_xor_sync(0xffffffffu, ps1, 2);
        l0 = l0 * corr0 + ps0;
        l1 = l1 * corr1 + ps1;

        #pragma unroll
        for (int nt = 0; nt < 16; nt++) {
            o[nt][0] *= corr0; o[nt][1] *= corr0;
            o[nt][2] *= corr1; o[nt][3] *= corr1;
        }

        #pragma unroll
        for (int ks = 0; ks < 4; ks++) {
            uint32_t ph[4], pl[4];
            split_pack(s[2*ks][0],   s[2*ks][1],   ph[0], pl[0]);
            split_pack(s[2*ks][2],   s[2*ks][3],   ph[1], pl[1]);
            split_pack(s[2*ks+1][0], s[2*ks+1][1], ph[2], pl[2]);
            split_pack(s[2*ks+1][2], s[2*ks+1][3], ph[3], pl[3]);
            #pragma unroll
            for (int dp = 0; dp < 8; dp++) {
                uint32_t vh[4], vl[4];
                uint32_t addr = sb + (uint32_t)(16 * ks) * VP + dp * 32 + v_add;
                ldsm_x4_t(vh[0], vh[1], vh[2], vh[3], addr + 2*KTB);
                ldsm_x4_t(vl[0], vl[1], vl[2], vl[3], addr + 3*KTB);
                mma_bf16(o[2*dp],   ph, vh[0], vh[1]);
                mma_bf16(o[2*dp],   ph, vl[0], vl[1]);
                mma_bf16(o[2*dp],   pl, vh[0], vh[1]);
                mma_bf16(o[2*dp+1], ph, vh[2], vh[3]);
                mma_bf16(o[2*dp+1], ph, vl[2], vl[3]);
                mma_bf16(o[2*dp+1], pl, vh[2], vh[3]);
            }
        }
        __syncthreads();
    }

    const float inv0 = 1.f / l0, inv1 = 1.f / l1;
    const size_t ob0 = (size_t)(b * SQ + row0) * HD + hc;
    const size_t ob1 = ob0 + (size_t)8 * HD;
    #pragma unroll
    for (int nt = 0; nt < 16; nt++) {
        int col = 8 * nt + c2;
        uint32_t hh, ll;
        split_pack(o[nt][0] * inv0, o[nt][1] * inv0, hh, ll);
        *(uint32_t*)&Ahi[ob0 + col] = hh;
        *(uint32_t*)&Alo[ob0 + col] = ll;
        split_pack(o[nt][2] * inv1, o[nt][3] * inv1, hh, ll);
        *(uint32_t*)&Ahi[ob1 + col] = hh;
        *(uint32_t*)&Alo[ob1 + col] = ll;
    }
}

// ---------------------------------------------------------------------------

extern "C" void kernel_launch(void* const* d_in, const int* in_sizes, int n_in,
                              void* d_out, int out_size)
{
    const float* X   = (const float*)d_in[0];
    const int*   msk = (const int*)  d_in[1];
    const float* Wq  = (const float*)d_in[2];
    const float* bq  = (const float*)d_in[3];
    const float* Wk  = (const float*)d_in[4];
    const float* bk  = (const float*)d_in[5];
    const float* Wv  = (const float*)d_in[6];
    const float* bv  = (const float*)d_in[7];
    const float* Wo  = (const float*)d_in[8];
    const float* bo  = (const float*)d_in[9];
    float* out = (float*)d_out;

    __nv_bfloat16 *Qhi, *Qlo, *Khi, *Klo, *Vhi, *Vlo, *Ahi, *Alo, *Xhi, *Xlo, *Wthi, *Wtlo;
    cudaGetSymbolAddress((void**)&Qhi, g_Qhi);
    cudaGetSymbolAddress((void**)&Qlo, g_Qlo);
    cudaGetSymbolAddress((void**)&Khi, g_Khi);
    cudaGetSymbolAddress((void**)&Klo, g_Klo);
    cudaGetSymbolAddress((void**)&Vhi, g_Vhi);
    cudaGetSymbolAddress((void**)&Vlo, g_Vlo);
    cudaGetSymbolAddress((void**)&Ahi, g_Ahi);
    cudaGetSymbolAddress((void**)&Alo, g_Alo);
    cudaGetSymbolAddress((void**)&Xhi, g_Xhi);
    cudaGetSymbolAddress((void**)&Xlo, g_Xlo);
    cudaGetSymbolAddress((void**)&Wthi, g_Wthi);
    cudaGetSymbolAddress((void**)&Wtlo, g_Wtlo);

    const size_t WSZ = (size_t)HD * HD;
    const int n4 = MR * HD / 4;

    cudaFuncSetAttribute(gemm_mma_kernel<0>,
                         cudaFuncAttributeMaxDynamicSharedMemorySize, GEMM_SMEM);
    cudaFuncSetAttribute(gemm_mma_kernel<1>,
                         cudaFuncAttributeMaxDynamicSharedMemorySize, GEMM_SMEM);
    cudaFuncSetAttribute(attn_mma_kernel,
                         cudaFuncAttributeMaxDynamicSharedMemorySize, ATTN_SMEM);

    // 1. bf16 hi/lo splits of X; batched weight transpose+split
    cvt_split_kernel<<<n4 / 256, 256>>>((const float4*)X, Xhi, Xlo, n4);
    dim3 wg(HD / 32, HD / 32, 4), wb(32, 8);
    cvt_wt_kernel<<<wg, wb>>>(Wq, Wk, Wv, Wo, Wthi, Wtlo);

    // 2. Fused Q/K/V projection (one launch; Wt slabs contiguous)
    dim3 gq(3 * HD / 128, MR / 128);   // (48, 32)
    gemm_mma_kernel<0><<<gq, 256, GEMM_SMEM>>>(
        Xhi, Xlo, Wthi, Wtlo, bq, bk, bv,
        Qhi, Qlo, Khi, Klo, Vhi, Vlo, nullptr);

    // 3. tensor-core flash attention -> split-bf16 A
    dim3 ga(SQ / 128, NH, BB);
    attn_mma_kernel<<<ga, 256, ATTN_SMEM>>>(Qhi, Qlo, Khi, Klo, Vhi, Vlo, msk, Ahi, Alo);

    // 4. output projection -> fp32 out
    dim3 go(HD / 128, MR / 128);       // (16, 32)
    gemm_mma_kernel<1><<<go, 256, GEMM_SMEM>>>(
        Ahi, Alo, Wthi + 3*WSZ, Wtlo + 3*WSZ, bo, bo, bo,
        nullptr, nullptr, nullptr, nullptr, nullptr, nullptr, out);
}